// round 6
// baseline (speedup 1.0000x reference)
#include <cuda_runtime.h>
#include <math.h>

// Problem dims
#define NB   16
#define TT   512
#define DD   512
#define NM   8
#define NH   8
#define DHD  64
#define OUTF 2048
#define CSIZE 8
#define SCAN_THREADS 512

// ---------------------------------------------------------------------------
// Scratch (static __device__ — no allocations allowed)
// ---------------------------------------------------------------------------
__device__ float g_M[NB][NM][DD];            // memory state
__device__ float g_QKV[NB][3][NM][DD];       // per-step Q/K/V of M rows
__device__ float g_part[NB][CSIZE][NM][2];   // LN partial (sum, sumsq)
__device__ float g_KVy[NB * TT][2 * DD];     // precomputed K,V of y_t
__device__ float g_MS[NB * TT][DD];          // summaries

// ---------------------------------------------------------------------------
// Init M = broadcast(mem_init)
// ---------------------------------------------------------------------------
__global__ void init_M_kernel(const float* __restrict__ mem_init) {
    int b = blockIdx.x;
    for (int idx = threadIdx.x; idx < NM * DD; idx += blockDim.x)
        ((float*)g_M[b])[idx] = mem_init[idx];
}

// ---------------------------------------------------------------------------
// Generic GEMM-NT: C[m][n] = act(bias[n] + sum_k A[m][k] * W[n][k]),  K = 512
// BM=BN=128, BK=16, 256 threads, 8x8 microtile. Optional embedding gather for A.
// ---------------------------------------------------------------------------
template <bool GATHER, bool RELU>
__global__ __launch_bounds__(256) void gemm_nt(
    const float* __restrict__ A, const int* __restrict__ ids,
    const float* __restrict__ emb,
    const float* __restrict__ W, const float* __restrict__ bias,
    float* __restrict__ C, int M, int N)
{
    __shared__ float As[16][132];
    __shared__ float Bs[16][132];

    const int tid = threadIdx.x;
    const int ty = tid >> 4;       // 0..15
    const int tx = tid & 15;       // 0..15
    const int m0 = blockIdx.y * 128;
    const int n0 = blockIdx.x * 128;

    float acc[8][8];
#pragma unroll
    for (int i = 0; i < 8; i++)
#pragma unroll
        for (int j = 0; j < 8; j++) acc[i][j] = 0.f;

    for (int kt = 0; kt < 512; kt += 16) {
#pragma unroll
        for (int s = 0; s < 2; s++) {
            int slot = tid + s * 256;       // 0..511
            int r = slot >> 2;              // 0..127
            int q = (slot & 3) * 4;         // 0,4,8,12
            float4 v, w;
            if (GATHER) {
                int id = ids[m0 + r];
                if (id != 0)
                    v = *(const float4*)(emb + (size_t)id * 512 + kt + q);
                else
                    v = make_float4(0.f, 0.f, 0.f, 0.f);
            } else {
                v = *(const float4*)(A + (size_t)(m0 + r) * 512 + kt + q);
            }
            w = *(const float4*)(W + (size_t)(n0 + r) * 512 + kt + q);
            As[q + 0][r] = v.x; As[q + 1][r] = v.y;
            As[q + 2][r] = v.z; As[q + 3][r] = v.w;
            Bs[q + 0][r] = w.x; Bs[q + 1][r] = w.y;
            Bs[q + 2][r] = w.z; Bs[q + 3][r] = w.w;
        }
        __syncthreads();
#pragma unroll
        for (int kk = 0; kk < 16; kk++) {
            const float4 a0 = *(const float4*)&As[kk][ty * 8];
            const float4 a1 = *(const float4*)&As[kk][ty * 8 + 4];
            const float4 b0 = *(const float4*)&Bs[kk][tx * 8];
            const float4 b1 = *(const float4*)&Bs[kk][tx * 8 + 4];
            float ar[8] = {a0.x, a0.y, a0.z, a0.w, a1.x, a1.y, a1.z, a1.w};
            float br[8] = {b0.x, b0.y, b0.z, b0.w, b1.x, b1.y, b1.z, b1.w};
#pragma unroll
            for (int i = 0; i < 8; i++)
#pragma unroll
                for (int j = 0; j < 8; j++)
                    acc[i][j] = fmaf(ar[i], br[j], acc[i][j]);
        }
        __syncthreads();
    }

#pragma unroll
    for (int i = 0; i < 8; i++) {
        int m = m0 + ty * 8 + i;
#pragma unroll
        for (int j = 0; j < 8; j++) {
            int n = n0 + tx * 8 + j;
            float v = acc[i][j] + bias[n];
            if (RELU) v = fmaxf(v, 0.f);
            C[(size_t)m * N + n] = v;
        }
    }
}

// ---------------------------------------------------------------------------
// Scan kernel: one cluster of 8 CTAs per batch, 512 threads per CTA.
// CTA `rank` owns output columns [rank*64, rank*64+64) of every projection.
// ---------------------------------------------------------------------------
struct SmemScan {
    float Xs[NM][DD];            // M rows
    float Qs[NM][DD];
    float Ks[NM + 1][DD];
    float Vs[NM + 1][DD];
    float Os[NM][DD];            // attention output
    float Sc[NM][NH][NM + 1];    // scores -> attn weights (in place)
    float resid[NM][64];         // residual tile / LN output tile
    float wpart[NM][2][2];       // per-warp-half (sum, sumsq)
};

__device__ __forceinline__ void cluster_sync_all() {
    asm volatile("barrier.cluster.arrive.aligned;" ::: "memory");
    asm volatile("barrier.cluster.wait.aligned;" ::: "memory");
}

__global__ __launch_bounds__(SCAN_THREADS, 1) __cluster_dims__(CSIZE, 1, 1)
void scan_kernel(const float* __restrict__ Wqkv, const float* __restrict__ bqkv,
                 const float* __restrict__ Wo,   const float* __restrict__ bo,
                 const float* __restrict__ lng,  const float* __restrict__ lnb)
{
    extern __shared__ char smem_raw[];
    SmemScan* sm = (SmemScan*)smem_raw;

    const int tid = threadIdx.x;
    const int rank = blockIdx.x;          // 0..7 (== cluster cta rank)
    const int b = blockIdx.y;             // batch
    const int colLocal = tid >> 3;        // 0..63
    const int col = rank * 64 + colLocal; // global output column
    const int ks = tid & 7;               // k-split lane
    const int kbase = ks * 64;

    for (int t = 0; t < TT; t++) {
        // --- load M into Xs --------------------------------------------------
        {
            const float4* msrc = (const float4*)&g_M[b][0][0];
            float4* xd = (float4*)&sm->Xs[0][0];
            xd[tid] = msrc[tid];
            xd[tid + 512] = msrc[tid + 512];
        }
        __syncthreads();

        // --- phase 1: Q/K/V projections of M rows ---------------------------
#pragma unroll 1
        for (int p = 0; p < 3; p++) {
            const float* Wr = Wqkv + ((size_t)(p * DD + col)) * DD + kbase;
            float acc[NM];
#pragma unroll
            for (int i = 0; i < NM; i++) acc[i] = 0.f;
#pragma unroll 4
            for (int kk = 0; kk < 64; kk += 4) {
                float4 w = *(const float4*)(Wr + kk);
#pragma unroll
                for (int i = 0; i < NM; i++) {
                    float4 x = *(const float4*)&sm->Xs[i][kbase + kk];
                    acc[i] = fmaf(w.x, x.x, fmaf(w.y, x.y,
                              fmaf(w.z, x.z, fmaf(w.w, x.w, acc[i]))));
                }
            }
#pragma unroll
            for (int i = 0; i < NM; i++) {
                acc[i] += __shfl_xor_sync(0xffffffffu, acc[i], 1);
                acc[i] += __shfl_xor_sync(0xffffffffu, acc[i], 2);
                acc[i] += __shfl_xor_sync(0xffffffffu, acc[i], 4);
            }
            if (ks == 0) {
                float bias = bqkv[p * DD + col];
#pragma unroll
                for (int i = 0; i < NM; i++)
                    g_QKV[b][p][i][col] = acc[i] + bias;
            }
        }
        cluster_sync_all();   // #1: QKV visible cluster-wide

        // --- phase 2a: load Q,K,V (+ y_t row from precomputed KVy) ----------
        {
            const float4* qsrc = (const float4*)&g_QKV[b][0][0][0];
            const float4* ksrc = (const float4*)&g_QKV[b][1][0][0];
            const float4* vsrc = (const float4*)&g_QKV[b][2][0][0];
            const float4* kvy  = (const float4*)&g_KVy[b * TT + t][0];
            float4* qd = (float4*)&sm->Qs[0][0];
            float4* kd = (float4*)&sm->Ks[0][0];
            float4* vd = (float4*)&sm->Vs[0][0];
            qd[tid] = qsrc[tid];           qd[tid + 512] = qsrc[tid + 512];
            kd[tid] = ksrc[tid];           kd[tid + 512] = ksrc[tid + 512];
            vd[tid] = vsrc[tid];           vd[tid + 512] = vsrc[tid + 512];
            if (tid < 128) {
                kd[1024 + tid] = kvy[tid];
                vd[1024 + tid] = kvy[128 + tid];
            }
        }
        __syncthreads();

        // --- scores: s[i][h][j] = q_i,h . k_j,h / 8 --------------------------
        for (int idx = tid; idx < NM * NH * (NM + 1); idx += SCAN_THREADS) {
            int i = idx / (NH * (NM + 1));
            int rem = idx - i * (NH * (NM + 1));
            int h = rem / (NM + 1);
            int j = rem - h * (NM + 1);
            const float* q = &sm->Qs[i][h * DHD];
            const float* kk = &sm->Ks[j][h * DHD];
            float s = 0.f;
#pragma unroll
            for (int d = 0; d < DHD; d += 4) {
                float4 a = *(const float4*)(q + d);
                float4 c = *(const float4*)(kk + d);
                s = fmaf(a.x, c.x, fmaf(a.y, c.y,
                     fmaf(a.z, c.z, fmaf(a.w, c.w, s))));
            }
            sm->Sc[i][h][j] = s * 0.125f;
        }
        __syncthreads();

        // --- softmax over 9 kv entries ---------------------------------------
        if (tid < NM * NH) {
            int i = tid >> 3, h = tid & 7;
            float mx = -1e30f;
#pragma unroll
            for (int j = 0; j < NM + 1; j++) mx = fmaxf(mx, sm->Sc[i][h][j]);
            float e[NM + 1];
            float sum = 0.f;
#pragma unroll
            for (int j = 0; j < NM + 1; j++) {
                e[j] = expf(sm->Sc[i][h][j] - mx);
                sum += e[j];
            }
            float inv = 1.f / sum;
#pragma unroll
            for (int j = 0; j < NM + 1; j++) sm->Sc[i][h][j] = e[j] * inv;
        }
        __syncthreads();

        // --- O = A @ V --------------------------------------------------------
#pragma unroll
        for (int rep = 0; rep < 8; rep++) {
            int idx = rep * SCAN_THREADS + tid;
            int i = idx >> 9, c = idx & (DD - 1), h = c >> 6;
            float o = 0.f;
#pragma unroll
            for (int j = 0; j < NM + 1; j++)
                o = fmaf(sm->Sc[i][h][j], sm->Vs[j][c], o);
            sm->Os[i][c] = o;
        }
        __syncthreads();

        // --- out-projection tile + residual ----------------------------------
        {
            const float* Wr = Wo + (size_t)col * DD + kbase;
            float acc[NM];
#pragma unroll
            for (int i = 0; i < NM; i++) acc[i] = 0.f;
#pragma unroll 4
            for (int kk = 0; kk < 64; kk += 4) {
                float4 w = *(const float4*)(Wr + kk);
#pragma unroll
                for (int i = 0; i < NM; i++) {
                    float4 x = *(const float4*)&sm->Os[i][kbase + kk];
                    acc[i] = fmaf(w.x, x.x, fmaf(w.y, x.y,
                              fmaf(w.z, x.z, fmaf(w.w, x.w, acc[i]))));
                }
            }
#pragma unroll
            for (int i = 0; i < NM; i++) {
                acc[i] += __shfl_xor_sync(0xffffffffu, acc[i], 1);
                acc[i] += __shfl_xor_sync(0xffffffffu, acc[i], 2);
                acc[i] += __shfl_xor_sync(0xffffffffu, acc[i], 4);
            }
            if (ks == 0) {
                float bias = bo[col];
#pragma unroll
                for (int i = 0; i < NM; i++)
                    sm->resid[i][colLocal] = sm->Xs[i][col] + acc[i] + bias;
            }
        }
        __syncthreads();

        // --- LN partial stats over this CTA's 64 columns ----------------------
        {
            int i = tid >> 6, c = tid & 63;
            float v = sm->resid[i][c];
            float s1 = v, s2 = v * v;
#pragma unroll
            for (int off = 16; off; off >>= 1) {
                s1 += __shfl_xor_sync(0xffffffffu, s1, off);
                s2 += __shfl_xor_sync(0xffffffffu, s2, off);
            }
            if ((tid & 31) == 0) {
                int half = (tid >> 5) & 1;
                sm->wpart[i][half][0] = s1;
                sm->wpart[i][half][1] = s2;
            }
        }
        __syncthreads();
        if (tid < NM) {
            g_part[b][rank][tid][0] = sm->wpart[tid][0][0] + sm->wpart[tid][1][0];
            g_part[b][rank][tid][1] = sm->wpart[tid][0][1] + sm->wpart[tid][1][1];
        }
        cluster_sync_all();   // #2: partial stats visible

        // --- LN finalize, write M_new, summary ---------------------------------
        {
            int i = tid >> 6, c = tid & 63;
            float S = 0.f, SS = 0.f;
#pragma unroll
            for (int r2 = 0; r2 < CSIZE; r2++) {
                S  += g_part[b][r2][i][0];
                SS += g_part[b][r2][i][1];
            }
            float mu = S * (1.f / 512.f);
            float var = SS * (1.f / 512.f) - mu * mu;
            float inv = rsqrtf(var + 1e-5f);
            int cc = rank * 64 + c;
            float x = sm->resid[i][c];
            float y = (x - mu) * inv * lng[cc] + lnb[cc];
            g_M[b][i][cc] = y;
            sm->resid[i][c] = y;
        }
        __syncthreads();
        if (tid < 64) {
            float s = 0.f;
#pragma unroll
            for (int i = 0; i < NM; i++) s += sm->resid[i][tid];
            g_MS[b * TT + t][rank * 64 + tid] = s * 0.125f;
        }
        cluster_sync_all();   // #3: M_new visible for next step
    }
}

// ---------------------------------------------------------------------------
// Launch
// ---------------------------------------------------------------------------
extern "C" void kernel_launch(void* const* d_in, const int* in_sizes, int n_in,
                              void* d_out, int out_size) {
    const int*   ids        = (const int*)d_in[0];
    const float* embedding  = (const float*)d_in[1];
    const float* mem_init   = (const float*)d_in[2];
    const float* in_proj_w  = (const float*)d_in[3];
    const float* in_proj_b  = (const float*)d_in[4];
    const float* out_proj_w = (const float*)d_in[5];
    const float* out_proj_b = (const float*)d_in[6];
    const float* ln_g       = (const float*)d_in[7];
    const float* ln_b       = (const float*)d_in[8];
    const float* proj_w     = (const float*)d_in[9];
    const float* proj_b     = (const float*)d_in[10];
    float* out = (float*)d_out;

    void *pKVy = nullptr, *pMS = nullptr;
    cudaGetSymbolAddress(&pKVy, g_KVy);
    cudaGetSymbolAddress(&pMS, g_MS);

    cudaFuncSetAttribute(scan_kernel,
                         cudaFuncAttributeMaxDynamicSharedMemorySize,
                         (int)sizeof(SmemScan));

    // 1) init memory state
    init_M_kernel<<<NB, 256>>>(mem_init);

    // 2) precompute K,V projections of all tokens (gather GEMM):
    //    KVy[bt, 0:512]   = emb_bt @ Wk^T + bk
    //    KVy[bt, 512:1024]= emb_bt @ Wv^T + bv
    {
        dim3 grid((2 * DD) / 128, (NB * TT) / 128);
        gemm_nt<true, false><<<grid, 256>>>(
            nullptr, ids, embedding,
            in_proj_w + (size_t)DD * DD, in_proj_b + DD,
            (float*)pKVy, NB * TT, 2 * DD);
    }

    // 3) sequential scan: 16 clusters (one per batch) x 8 CTAs
    scan_kernel<<<dim3(CSIZE, NB), SCAN_THREADS, sizeof(SmemScan)>>>(
        in_proj_w, in_proj_b, out_proj_w, out_proj_b, ln_g, ln_b);

    // 4) final projection: relu(MS @ proj_w^T + proj_b)
    {
        dim3 grid(OUTF / 128, (NB * TT) / 128);
        gemm_nt<false, true><<<grid, 256>>>(
            (const float*)pMS, nullptr, nullptr,
            proj_w, proj_b, out, NB * TT, OUTF);
    }
}

// round 7
// speedup vs baseline: 2.0114x; 2.0114x over previous
#include <cuda_runtime.h>
#include <math.h>

// Problem dims
#define NB   16
#define TT   512
#define DD   512
#define NM   8
#define NH   8
#define DHD  64
#define OUTF 2048
#define CSIZE 8
#define SCAN_THREADS 512

// ---------------------------------------------------------------------------
// Scratch (static __device__ — no allocations allowed)
// ---------------------------------------------------------------------------
__device__ __align__(16) float g_Wpack[4 * 16 * 512 * 8 * 4]; // [pp][kk][col][ks][4]
__device__ __align__(16) float g_QKV[NB][3][NM][DD];          // per-step Q/K/V of M rows
__device__ __align__(16) float g_resid[NB][NM][DD];           // residual (pre-LN)
__device__ float g_part[NB][CSIZE][NM][2];                    // LN partial (sum, sumsq)
__device__ __align__(16) float g_KVy[NB * TT][2 * DD];        // precomputed K,V of y_t
__device__ __align__(16) float g_MS[NB * TT][DD];             // summaries

// ---------------------------------------------------------------------------
// f32x2 packed helpers
// ---------------------------------------------------------------------------
__device__ __forceinline__ void fma2(unsigned long long& d,
                                     unsigned long long a, unsigned long long b) {
    asm("fma.rn.f32x2 %0, %1, %2, %0;" : "+l"(d) : "l"(a), "l"(b));
}
__device__ __forceinline__ float2 u2f2(unsigned long long v) {
    float2 f; asm("mov.b64 {%0,%1}, %2;" : "=f"(f.x), "=f"(f.y) : "l"(v)); return f;
}

// ---------------------------------------------------------------------------
// Weight repack: g_Wpack[(((pp*16+kk)*512+col)*8+ks)*4+e] = W[col][ks*64+kk*4+e]
// pp 0..2 -> in_proj rows [pp*512, pp*512+512);  pp=3 -> out_proj
// ---------------------------------------------------------------------------
__global__ void repack_kernel(const float* __restrict__ Wqkv,
                              const float* __restrict__ Wo) {
    int idx = blockIdx.x * 256 + threadIdx.x;   // 0 .. 2^20-1
    int e   = idx & 3;
    int ks  = (idx >> 2) & 7;
    int col = (idx >> 5) & 511;
    int kk  = (idx >> 14) & 15;
    int pp  = idx >> 18;
    int k   = ks * 64 + kk * 4 + e;
    float v = (pp < 3) ? Wqkv[((size_t)(pp * 512 + col)) * 512 + k]
                       : Wo[(size_t)col * 512 + k];
    g_Wpack[idx] = v;
}

// ---------------------------------------------------------------------------
// Generic GEMM-NT (unchanged, passing): C = act(bias + A @ W^T), K=512
// ---------------------------------------------------------------------------
template <bool GATHER, bool RELU>
__global__ __launch_bounds__(256) void gemm_nt(
    const float* __restrict__ A, const int* __restrict__ ids,
    const float* __restrict__ emb,
    const float* __restrict__ W, const float* __restrict__ bias,
    float* __restrict__ C, int M, int N)
{
    __shared__ float As[16][132];
    __shared__ float Bs[16][132];

    const int tid = threadIdx.x;
    const int ty = tid >> 4;
    const int tx = tid & 15;
    const int m0 = blockIdx.y * 128;
    const int n0 = blockIdx.x * 128;

    float acc[8][8];
#pragma unroll
    for (int i = 0; i < 8; i++)
#pragma unroll
        for (int j = 0; j < 8; j++) acc[i][j] = 0.f;

    for (int kt = 0; kt < 512; kt += 16) {
#pragma unroll
        for (int s = 0; s < 2; s++) {
            int slot = tid + s * 256;
            int r = slot >> 2;
            int q = (slot & 3) * 4;
            float4 v, w;
            if (GATHER) {
                int id = ids[m0 + r];
                if (id != 0)
                    v = *(const float4*)(emb + (size_t)id * 512 + kt + q);
                else
                    v = make_float4(0.f, 0.f, 0.f, 0.f);
            } else {
                v = *(const float4*)(A + (size_t)(m0 + r) * 512 + kt + q);
            }
            w = *(const float4*)(W + (size_t)(n0 + r) * 512 + kt + q);
            As[q + 0][r] = v.x; As[q + 1][r] = v.y;
            As[q + 2][r] = v.z; As[q + 3][r] = v.w;
            Bs[q + 0][r] = w.x; Bs[q + 1][r] = w.y;
            Bs[q + 2][r] = w.z; Bs[q + 3][r] = w.w;
        }
        __syncthreads();
#pragma unroll
        for (int kk = 0; kk < 16; kk++) {
            const float4 a0 = *(const float4*)&As[kk][ty * 8];
            const float4 a1 = *(const float4*)&As[kk][ty * 8 + 4];
            const float4 b0 = *(const float4*)&Bs[kk][tx * 8];
            const float4 b1 = *(const float4*)&Bs[kk][tx * 8 + 4];
            float ar[8] = {a0.x, a0.y, a0.z, a0.w, a1.x, a1.y, a1.z, a1.w};
            float br[8] = {b0.x, b0.y, b0.z, b0.w, b1.x, b1.y, b1.z, b1.w};
#pragma unroll
            for (int i = 0; i < 8; i++)
#pragma unroll
                for (int j = 0; j < 8; j++)
                    acc[i][j] = fmaf(ar[i], br[j], acc[i][j]);
        }
        __syncthreads();
    }

#pragma unroll
    for (int i = 0; i < 8; i++) {
        int m = m0 + ty * 8 + i;
#pragma unroll
        for (int j = 0; j < 8; j++) {
            int n = n0 + tx * 8 + j;
            float v = acc[i][j] + bias[n];
            if (RELU) v = fmaxf(v, 0.f);
            C[(size_t)m * N + n] = v;
        }
    }
}

// ---------------------------------------------------------------------------
// Scan kernel: one cluster of 8 CTAs per batch, 512 threads per CTA.
// CTA `rank` owns output columns [rank*64, rank*64+64) of every projection.
// Full normalized state Xs lives in every CTA's smem.
// ---------------------------------------------------------------------------
struct SmemScan {
    float Xs[NM][DD];            // normalized memory state (all columns)
    float Qs[NM][DD];
    float Ks[NM + 1][DD];
    float Vs[NM + 1][DD];
    float Os[NM][DD];            // attention output
    float Sc[NM][NH][NM + 1];    // scores -> attn weights
    float resid[NM][64];         // residual tile (own columns)
    float wpart[NM][2][2];
    float muinv[NM][2];
};

__device__ __forceinline__ void cluster_sync_all() {
    asm volatile("barrier.cluster.arrive.aligned;" ::: "memory");
    asm volatile("barrier.cluster.wait.aligned;" ::: "memory");
}

__global__ __launch_bounds__(SCAN_THREADS, 1) __cluster_dims__(CSIZE, 1, 1)
void scan_kernel(const float* __restrict__ mem_init,
                 const float* __restrict__ bqkv,
                 const float* __restrict__ bo,
                 const float* __restrict__ lng, const float* __restrict__ lnb)
{
    extern __shared__ char smem_raw[];
    SmemScan* sm = (SmemScan*)smem_raw;

    const int tid = threadIdx.x;
    const int rank = blockIdx.x;          // 0..7 == cluster cta rank
    const int b = blockIdx.y;             // batch
    const int colLocal = tid >> 3;        // 0..63
    const int col = rank * 64 + colLocal; // global output column
    const int ks = tid & 7;               // k-split lane
    const int kbase = ks * 64;
    const ulonglong2* Wp = (const ulonglong2*)g_Wpack;
    const int wbase = col * 8 + ks;       // float4 index within a kk-plane

    // Hoisted per-thread constants
    const float bq_r = bqkv[col];
    const float bk_r = bqkv[DD + col];
    const float bv_r = bqkv[2 * DD + col];
    const float bo_r = bo[col];
    const float4 lng0 = ((const float4*)lng)[tid & 127];
    const float4 lnb0 = ((const float4*)lnb)[tid & 127];
    const float4 lng1 = ((const float4*)lng)[(tid + 512) & 127];
    const float4 lnb1 = ((const float4*)lnb)[(tid + 512) & 127];

    // Init Xs = mem_init (M0 broadcast)
    {
        const float4* src = (const float4*)mem_init;
        float4* xd = (float4*)&sm->Xs[0][0];
        xd[tid] = src[tid];
        xd[tid + 512] = src[tid + 512];
    }
    __syncthreads();

    for (int t = 0; t < TT; t++) {
        // --- phase 1: fused Q/K/V projections (f32x2) -------------------------
        {
            unsigned long long acc[3][NM];
#pragma unroll
            for (int p = 0; p < 3; p++)
#pragma unroll
                for (int i = 0; i < NM; i++) acc[p][i] = 0ull;

#pragma unroll 4
            for (int kk = 0; kk < 16; kk++) {
                ulonglong2 wq = Wp[(kk)*4096 + wbase];
                ulonglong2 wk = Wp[(16 + kk) * 4096 + wbase];
                ulonglong2 wv = Wp[(32 + kk) * 4096 + wbase];
                const char* xb = (const char*)&sm->Xs[0][kbase + kk * 4];
#pragma unroll
                for (int i = 0; i < NM; i++) {
                    ulonglong2 x = *(const ulonglong2*)(xb + i * (DD * 4));
                    fma2(acc[0][i], x.x, wq.x); fma2(acc[0][i], x.y, wq.y);
                    fma2(acc[1][i], x.x, wk.x); fma2(acc[1][i], x.y, wk.y);
                    fma2(acc[2][i], x.x, wv.x); fma2(acc[2][i], x.y, wv.y);
                }
            }
#pragma unroll
            for (int p = 0; p < 3; p++) {
                float bias = (p == 0) ? bq_r : (p == 1) ? bk_r : bv_r;
#pragma unroll
                for (int i = 0; i < NM; i++) {
                    float2 f = u2f2(acc[p][i]);
                    float a = f.x + f.y;
                    a += __shfl_xor_sync(0xffffffffu, a, 1);
                    a += __shfl_xor_sync(0xffffffffu, a, 2);
                    a += __shfl_xor_sync(0xffffffffu, a, 4);
                    if (ks == 0) g_QKV[b][p][i][col] = a + bias;
                }
            }
        }
        cluster_sync_all();   // #1: QKV visible cluster-wide

        // --- phase 2: load Q,K,V (+ y_t row from precomputed KVy) -------------
        {
            const float4* qsrc = (const float4*)&g_QKV[b][0][0][0];
            const float4* ksrc = (const float4*)&g_QKV[b][1][0][0];
            const float4* vsrc = (const float4*)&g_QKV[b][2][0][0];
            const float4* kvy  = (const float4*)&g_KVy[b * TT + t][0];
            float4* qd = (float4*)&sm->Qs[0][0];
            float4* kd = (float4*)&sm->Ks[0][0];
            float4* vd = (float4*)&sm->Vs[0][0];
            qd[tid] = qsrc[tid];           qd[tid + 512] = qsrc[tid + 512];
            kd[tid] = ksrc[tid];           kd[tid + 512] = ksrc[tid + 512];
            vd[tid] = vsrc[tid];           vd[tid + 512] = vsrc[tid + 512];
            if (tid < 128) {
                kd[1024 + tid] = kvy[tid];
                vd[1024 + tid] = kvy[128 + tid];
            }
        }
        __syncthreads();

        // --- scores -----------------------------------------------------------
        for (int idx = tid; idx < NM * NH * (NM + 1); idx += SCAN_THREADS) {
            int i = idx / (NH * (NM + 1));
            int rem = idx - i * (NH * (NM + 1));
            int h = rem / (NM + 1);
            int j = rem - h * (NM + 1);
            const float* q = &sm->Qs[i][h * DHD];
            const float* kk = &sm->Ks[j][h * DHD];
            float s = 0.f;
#pragma unroll
            for (int d = 0; d < DHD; d += 4) {
                float4 a = *(const float4*)(q + d);
                float4 c = *(const float4*)(kk + d);
                s = fmaf(a.x, c.x, fmaf(a.y, c.y,
                     fmaf(a.z, c.z, fmaf(a.w, c.w, s))));
            }
            sm->Sc[i][h][j] = s * 0.125f;
        }
        __syncthreads();

        // --- softmax over 9 kv entries -----------------------------------------
        if (tid < NM * NH) {
            int i = tid >> 3, h = tid & 7;
            float mx = -1e30f;
#pragma unroll
            for (int j = 0; j < NM + 1; j++) mx = fmaxf(mx, sm->Sc[i][h][j]);
            float e[NM + 1];
            float sum = 0.f;
#pragma unroll
            for (int j = 0; j < NM + 1; j++) {
                e[j] = expf(sm->Sc[i][h][j] - mx);
                sum += e[j];
            }
            float inv = 1.f / sum;
#pragma unroll
            for (int j = 0; j < NM + 1; j++) sm->Sc[i][h][j] = e[j] * inv;
        }
        __syncthreads();

        // --- O = A @ V ----------------------------------------------------------
#pragma unroll
        for (int rep = 0; rep < 8; rep++) {
            int idx = rep * SCAN_THREADS + tid;
            int i = idx >> 9, c = idx & (DD - 1), h = c >> 6;
            float o = 0.f;
#pragma unroll
            for (int j = 0; j < NM + 1; j++)
                o = fmaf(sm->Sc[i][h][j], sm->Vs[j][c], o);
            sm->Os[i][c] = o;
        }
        __syncthreads();

        // --- out-projection tile + residual (f32x2) -----------------------------
        {
            unsigned long long acc[NM];
#pragma unroll
            for (int i = 0; i < NM; i++) acc[i] = 0ull;
#pragma unroll 4
            for (int kk = 0; kk < 16; kk++) {
                ulonglong2 wo = Wp[(48 + kk) * 4096 + wbase];
                const char* xb = (const char*)&sm->Os[0][kbase + kk * 4];
#pragma unroll
                for (int i = 0; i < NM; i++) {
                    ulonglong2 x = *(const ulonglong2*)(xb + i * (DD * 4));
                    fma2(acc[i], x.x, wo.x);
                    fma2(acc[i], x.y, wo.y);
                }
            }
#pragma unroll
            for (int i = 0; i < NM; i++) {
                float2 f = u2f2(acc[i]);
                float a = f.x + f.y;
                a += __shfl_xor_sync(0xffffffffu, a, 1);
                a += __shfl_xor_sync(0xffffffffu, a, 2);
                a += __shfl_xor_sync(0xffffffffu, a, 4);
                if (ks == 0) {
                    float r = sm->Xs[i][col] + a + bo_r;
                    sm->resid[i][colLocal] = r;
                    g_resid[b][i][col] = r;
                }
            }
        }
        __syncthreads();

        // --- LN partial stats over this CTA's 64 columns -------------------------
        {
            int i = tid >> 6, c = tid & 63;
            float v = sm->resid[i][c];
            float s1 = v, s2 = v * v;
#pragma unroll
            for (int off = 16; off; off >>= 1) {
                s1 += __shfl_xor_sync(0xffffffffu, s1, off);
                s2 += __shfl_xor_sync(0xffffffffu, s2, off);
            }
            if ((tid & 31) == 0) {
                int half = (tid >> 5) & 1;
                sm->wpart[i][half][0] = s1;
                sm->wpart[i][half][1] = s2;
            }
        }
        __syncthreads();
        if (tid < NM) {
            g_part[b][rank][tid][0] = sm->wpart[tid][0][0] + sm->wpart[tid][1][0];
            g_part[b][rank][tid][1] = sm->wpart[tid][0][1] + sm->wpart[tid][1][1];
        }
        cluster_sync_all();   // #2: resid + partial stats visible

        // --- LN finalize (redundantly per CTA), rebuild full Xs -------------------
        if (tid < NM) {
            float S = 0.f, SS = 0.f;
#pragma unroll
            for (int r2 = 0; r2 < CSIZE; r2++) {
                S  += g_part[b][r2][tid][0];
                SS += g_part[b][r2][tid][1];
            }
            float mu = S * (1.f / 512.f);
            float var = SS * (1.f / 512.f) - mu * mu;
            sm->muinv[tid][0] = mu;
            sm->muinv[tid][1] = rsqrtf(var + 1e-5f);
        }
        __syncthreads();
        {
            const float4* rsrc = (const float4*)&g_resid[b][0][0];
            float4* xd = (float4*)&sm->Xs[0][0];
            {
                int v = tid;
                int i = v >> 7;
                float mu = sm->muinv[i][0], inv = sm->muinv[i][1];
                float4 r = rsrc[v];
                float4 y;
                y.x = (r.x - mu) * inv * lng0.x + lnb0.x;
                y.y = (r.y - mu) * inv * lng0.y + lnb0.y;
                y.z = (r.z - mu) * inv * lng0.z + lnb0.z;
                y.w = (r.w - mu) * inv * lng0.w + lnb0.w;
                xd[v] = y;
            }
            {
                int v = tid + 512;
                int i = v >> 7;
                float mu = sm->muinv[i][0], inv = sm->muinv[i][1];
                float4 r = rsrc[v];
                float4 y;
                y.x = (r.x - mu) * inv * lng1.x + lnb1.x;
                y.y = (r.y - mu) * inv * lng1.y + lnb1.y;
                y.z = (r.z - mu) * inv * lng1.z + lnb1.z;
                y.w = (r.w - mu) * inv * lng1.w + lnb1.w;
                xd[v] = y;
            }
        }
        __syncthreads();

        // --- summary (own 64 columns) ---------------------------------------------
        if (tid < 64) {
            int c = rank * 64 + tid;
            float s = 0.f;
#pragma unroll
            for (int i = 0; i < NM; i++) s += sm->Xs[i][c];
            g_MS[b * TT + t][c] = s * 0.125f;
        }
        __syncthreads();
    }
}

// ---------------------------------------------------------------------------
// Launch
// ---------------------------------------------------------------------------
extern "C" void kernel_launch(void* const* d_in, const int* in_sizes, int n_in,
                              void* d_out, int out_size) {
    const int*   ids        = (const int*)d_in[0];
    const float* embedding  = (const float*)d_in[1];
    const float* mem_init   = (const float*)d_in[2];
    const float* in_proj_w  = (const float*)d_in[3];
    const float* in_proj_b  = (const float*)d_in[4];
    const float* out_proj_w = (const float*)d_in[5];
    const float* out_proj_b = (const float*)d_in[6];
    const float* ln_g       = (const float*)d_in[7];
    const float* ln_b       = (const float*)d_in[8];
    const float* proj_w     = (const float*)d_in[9];
    const float* proj_b     = (const float*)d_in[10];
    float* out = (float*)d_out;

    void *pKVy = nullptr, *pMS = nullptr;
    cudaGetSymbolAddress(&pKVy, g_KVy);
    cudaGetSymbolAddress(&pMS, g_MS);

    cudaFuncSetAttribute(scan_kernel,
                         cudaFuncAttributeMaxDynamicSharedMemorySize,
                         (int)sizeof(SmemScan));

    // 1) repack weights for coalesced per-step loads
    repack_kernel<<<4096, 256>>>(in_proj_w, out_proj_w);

    // 2) precompute K,V projections of all tokens (gather GEMM)
    {
        dim3 grid((2 * DD) / 128, (NB * TT) / 128);
        gemm_nt<true, false><<<grid, 256>>>(
            nullptr, ids, embedding,
            in_proj_w + (size_t)DD * DD, in_proj_b + DD,
            (float*)pKVy, NB * TT, 2 * DD);
    }

    // 3) sequential scan: 16 clusters (one per batch) x 8 CTAs
    scan_kernel<<<dim3(CSIZE, NB), SCAN_THREADS, sizeof(SmemScan)>>>(
        mem_init, in_proj_b, out_proj_b, ln_g, ln_b);

    // 4) final projection: relu(MS @ proj_w^T + proj_b)
    {
        dim3 grid(OUTF / 128, (NB * TT) / 128);
        gemm_nt<false, true><<<grid, 256>>>(
            (const float*)pMS, nullptr, nullptr,
            proj_w, proj_b, out, NB * TT, OUTF);
    }
}

// round 8
// speedup vs baseline: 6.6579x; 3.3100x over previous
#include <cuda_runtime.h>
#include <math.h>

// Problem dims
#define NB   16
#define TT   512
#define DD   512
#define NM   8
#define NH   8
#define DHD  64
#define OUTF 2048
#define CSIZE 8
#define SCAN_THREADS 512

// ---------------------------------------------------------------------------
// Scratch (static __device__ — no allocations allowed)
// ---------------------------------------------------------------------------
__device__ __align__(16) float g_Wpack[4 * 16 * 512 * 8 * 4]; // [pp][kk][col][ks][4]
__device__ __align__(16) float g_QKV[NB][3][NM][DD];          // per-step Q/K/V of M rows
__device__ __align__(16) float g_resid[NB][NM][DD];           // residual (pre-LN)
__device__ float g_part[NB][CSIZE][NM][2];                    // LN partial (sum, sumsq)
__device__ __align__(16) float g_KVy[NB * TT][2 * DD];        // precomputed K,V of y_t
__device__ __align__(16) float g_MS[NB * TT][DD];             // summaries

// ---------------------------------------------------------------------------
// f32x2 packed helpers
// ---------------------------------------------------------------------------
__device__ __forceinline__ void fma2(unsigned long long& d,
                                     unsigned long long a, unsigned long long b) {
    asm("fma.rn.f32x2 %0, %1, %2, %0;" : "+l"(d) : "l"(a), "l"(b));
}
__device__ __forceinline__ float2 u2f2(unsigned long long v) {
    float2 f; asm("mov.b64 {%0,%1}, %2;" : "=f"(f.x), "=f"(f.y) : "l"(v)); return f;
}

// 16B-chunk swizzle: XOR bits [4:7) of the 16B index into bits [0:3).
// Kills the 8-way bank conflict of the ks-strided (256 B apart) reads.
__device__ __forceinline__ int sw16(int v) { return v ^ ((v >> 4) & 7); }
// scalar float index -> swizzled float index
__device__ __forceinline__ int swf(int f) {
    int c = f >> 2;
    return (c ^ ((c >> 4) & 7)) * 4 + (f & 3);
}

// ---------------------------------------------------------------------------
// Weight repack: g_Wpack[(((pp*16+kk)*512+col)*8+ks)*4+e] = W[col][ks*64+kk*4+e]
// pp 0..2 -> in_proj rows [pp*512, pp*512+512);  pp=3 -> out_proj
// ---------------------------------------------------------------------------
__global__ void repack_kernel(const float* __restrict__ Wqkv,
                              const float* __restrict__ Wo) {
    int idx = blockIdx.x * 256 + threadIdx.x;   // 0 .. 2^20-1
    int e   = idx & 3;
    int ks  = (idx >> 2) & 7;
    int col = (idx >> 5) & 511;
    int kk  = (idx >> 14) & 15;
    int pp  = idx >> 18;
    int k   = ks * 64 + kk * 4 + e;
    float v = (pp < 3) ? Wqkv[((size_t)(pp * 512 + col)) * 512 + k]
                       : Wo[(size_t)col * 512 + k];
    g_Wpack[idx] = v;
}

// ---------------------------------------------------------------------------
// Generic GEMM-NT: C = act(bias + A @ W^T), K=512
// ---------------------------------------------------------------------------
template <bool GATHER, bool RELU>
__global__ __launch_bounds__(256) void gemm_nt(
    const float* __restrict__ A, const int* __restrict__ ids,
    const float* __restrict__ emb,
    const float* __restrict__ W, const float* __restrict__ bias,
    float* __restrict__ C, int M, int N)
{
    __shared__ float As[16][132];
    __shared__ float Bs[16][132];

    const int tid = threadIdx.x;
    const int ty = tid >> 4;
    const int tx = tid & 15;
    const int m0 = blockIdx.y * 128;
    const int n0 = blockIdx.x * 128;

    float acc[8][8];
#pragma unroll
    for (int i = 0; i < 8; i++)
#pragma unroll
        for (int j = 0; j < 8; j++) acc[i][j] = 0.f;

    for (int kt = 0; kt < 512; kt += 16) {
#pragma unroll
        for (int s = 0; s < 2; s++) {
            int slot = tid + s * 256;
            int r = slot >> 2;
            int q = (slot & 3) * 4;
            float4 v, w;
            if (GATHER) {
                int id = ids[m0 + r];
                if (id != 0)
                    v = *(const float4*)(emb + (size_t)id * 512 + kt + q);
                else
                    v = make_float4(0.f, 0.f, 0.f, 0.f);
            } else {
                v = *(const float4*)(A + (size_t)(m0 + r) * 512 + kt + q);
            }
            w = *(const float4*)(W + (size_t)(n0 + r) * 512 + kt + q);
            As[q + 0][r] = v.x; As[q + 1][r] = v.y;
            As[q + 2][r] = v.z; As[q + 3][r] = v.w;
            Bs[q + 0][r] = w.x; Bs[q + 1][r] = w.y;
            Bs[q + 2][r] = w.z; Bs[q + 3][r] = w.w;
        }
        __syncthreads();
#pragma unroll
        for (int kk = 0; kk < 16; kk++) {
            const float4 a0 = *(const float4*)&As[kk][ty * 8];
            const float4 a1 = *(const float4*)&As[kk][ty * 8 + 4];
            const float4 b0 = *(const float4*)&Bs[kk][tx * 8];
            const float4 b1 = *(const float4*)&Bs[kk][tx * 8 + 4];
            float ar[8] = {a0.x, a0.y, a0.z, a0.w, a1.x, a1.y, a1.z, a1.w};
            float br[8] = {b0.x, b0.y, b0.z, b0.w, b1.x, b1.y, b1.z, b1.w};
#pragma unroll
            for (int i = 0; i < 8; i++)
#pragma unroll
                for (int j = 0; j < 8; j++)
                    acc[i][j] = fmaf(ar[i], br[j], acc[i][j]);
        }
        __syncthreads();
    }

#pragma unroll
    for (int i = 0; i < 8; i++) {
        int m = m0 + ty * 8 + i;
#pragma unroll
        for (int j = 0; j < 8; j++) {
            int n = n0 + tx * 8 + j;
            float v = acc[i][j] + bias[n];
            if (RELU) v = fmaxf(v, 0.f);
            C[(size_t)m * N + n] = v;
        }
    }
}

// ---------------------------------------------------------------------------
// Scan kernel: one cluster of 8 CTAs per batch, 512 threads per CTA.
// CTA `rank` owns output columns [rank*64, rank*64+64).
// Xs and Os use the sw16 swizzled layout (conflict-free ks-strided reads).
// ---------------------------------------------------------------------------
struct SmemScan {
    float Xs[NM][DD];            // normalized state (SWIZZLED layout)
    float Qs[NM][DD];
    float Ks[NM + 1][DD];
    float Vs[NM + 1][DD];
    float Os[NM][DD];            // attention output (SWIZZLED layout)
    float Sc[NM][NH][NM + 1];    // scores -> attn weights
    float resid[NM][64];         // residual tile (own columns)
    float wpart[NM][2][2];
    float muinv[NM][2];
};

__device__ __forceinline__ void cluster_sync_all() {
    asm volatile("barrier.cluster.arrive.aligned;" ::: "memory");
    asm volatile("barrier.cluster.wait.aligned;" ::: "memory");
}

__global__ __launch_bounds__(SCAN_THREADS, 1) __cluster_dims__(CSIZE, 1, 1)
void scan_kernel(const float* __restrict__ mem_init,
                 const float* __restrict__ bqkv,
                 const float* __restrict__ bo,
                 const float* __restrict__ lng, const float* __restrict__ lnb)
{
    extern __shared__ char smem_raw[];
    SmemScan* sm = (SmemScan*)smem_raw;

    const int tid = threadIdx.x;
    const int rank = blockIdx.x;          // 0..7 == cluster cta rank
    const int b = blockIdx.y;             // batch
    const int colLocal = tid >> 3;        // 0..63
    const int col = rank * 64 + colLocal; // global output column
    const int ks = tid & 7;               // k-split lane
    const ulonglong2* Wp = (const ulonglong2*)g_Wpack;
    const int wbase = col * 8 + ks;       // 16B index within a kk-plane

    const float4* Xs4 = (const float4*)sm->Xs;
    const float4* Os4 = (const float4*)sm->Os;
    float* Osf = (float*)sm->Os;
    float* Xsf = (float*)sm->Xs;

    // Hoisted per-thread constants
    const float bq_r = bqkv[col];
    const float bk_r = bqkv[DD + col];
    const float bv_r = bqkv[2 * DD + col];
    const float bo_r = bo[col];
    const float4 lng0 = ((const float4*)lng)[tid & 127];
    const float4 lnb0 = ((const float4*)lnb)[tid & 127];
    const float4 lng1 = ((const float4*)lng)[(tid + 512) & 127];
    const float4 lnb1 = ((const float4*)lnb)[(tid + 512) & 127];

    // Init Xs = mem_init (M0 broadcast), swizzled
    {
        const float4* src = (const float4*)mem_init;
        float4* xd = (float4*)sm->Xs;
        xd[sw16(tid)] = src[tid];
        xd[sw16(tid + 512)] = src[tid + 512];
    }
    __syncthreads();

    for (int t = 0; t < TT; t++) {
        // --- phase 1: fused Q/K/V projections (f32x2, swizzled Xs reads) ------
        {
            unsigned long long acc[3][NM];
#pragma unroll
            for (int p = 0; p < 3; p++)
#pragma unroll
                for (int i = 0; i < NM; i++) acc[p][i] = 0ull;

#pragma unroll 4
            for (int kk = 0; kk < 16; kk++) {
                ulonglong2 wq = Wp[(kk)*4096 + wbase];
                ulonglong2 wk = Wp[(16 + kk) * 4096 + wbase];
                ulonglong2 wv = Wp[(32 + kk) * 4096 + wbase];
                const int c0 = (ks * 16 + kk) ^ ks;   // swizzled chunk, row-invariant
#pragma unroll
                for (int i = 0; i < NM; i++) {
                    ulonglong2 x = *(const ulonglong2*)(Xs4 + i * 128 + c0);
                    fma2(acc[0][i], x.x, wq.x); fma2(acc[0][i], x.y, wq.y);
                    fma2(acc[1][i], x.x, wk.x); fma2(acc[1][i], x.y, wk.y);
                    fma2(acc[2][i], x.x, wv.x); fma2(acc[2][i], x.y, wv.y);
                }
            }
#pragma unroll
            for (int p = 0; p < 3; p++) {
                float bias = (p == 0) ? bq_r : (p == 1) ? bk_r : bv_r;
#pragma unroll
                for (int i = 0; i < NM; i++) {
                    float2 f = u2f2(acc[p][i]);
                    float a = f.x + f.y;
                    a += __shfl_xor_sync(0xffffffffu, a, 1);
                    a += __shfl_xor_sync(0xffffffffu, a, 2);
                    a += __shfl_xor_sync(0xffffffffu, a, 4);
                    if (ks == 0) g_QKV[b][p][i][col] = a + bias;
                }
            }
        }
        cluster_sync_all();   // #1: QKV visible cluster-wide

        // --- phase 2: load Q,K,V (+ y_t row from precomputed KVy) -------------
        {
            const float4* qsrc = (const float4*)&g_QKV[b][0][0][0];
            const float4* ksrc = (const float4*)&g_QKV[b][1][0][0];
            const float4* vsrc = (const float4*)&g_QKV[b][2][0][0];
            const float4* kvy  = (const float4*)&g_KVy[b * TT + t][0];
            float4* qd = (float4*)&sm->Qs[0][0];
            float4* kd = (float4*)&sm->Ks[0][0];
            float4* vd = (float4*)&sm->Vs[0][0];
            qd[tid] = qsrc[tid];           qd[tid + 512] = qsrc[tid + 512];
            kd[tid] = ksrc[tid];           kd[tid + 512] = ksrc[tid + 512];
            vd[tid] = vsrc[tid];           vd[tid + 512] = vsrc[tid + 512];
            if (tid < 128) {
                kd[1024 + tid] = kvy[tid];
                vd[1024 + tid] = kvy[128 + tid];
            }
        }
        __syncthreads();

        // --- scores -----------------------------------------------------------
        for (int idx = tid; idx < NM * NH * (NM + 1); idx += SCAN_THREADS) {
            int i = idx / (NH * (NM + 1));
            int rem = idx - i * (NH * (NM + 1));
            int h = rem / (NM + 1);
            int j = rem - h * (NM + 1);
            const float* q = &sm->Qs[i][h * DHD];
            const float* kk = &sm->Ks[j][h * DHD];
            float s = 0.f;
#pragma unroll
            for (int d = 0; d < DHD; d += 4) {
                float4 a = *(const float4*)(q + d);
                float4 c = *(const float4*)(kk + d);
                s = fmaf(a.x, c.x, fmaf(a.y, c.y,
                     fmaf(a.z, c.z, fmaf(a.w, c.w, s))));
            }
            sm->Sc[i][h][j] = s * 0.125f;
        }
        __syncthreads();

        // --- softmax over 9 kv entries -----------------------------------------
        if (tid < NM * NH) {
            int i = tid >> 3, h = tid & 7;
            float mx = -1e30f;
#pragma unroll
            for (int j = 0; j < NM + 1; j++) mx = fmaxf(mx, sm->Sc[i][h][j]);
            float e[NM + 1];
            float sum = 0.f;
#pragma unroll
            for (int j = 0; j < NM + 1; j++) {
                e[j] = expf(sm->Sc[i][h][j] - mx);
                sum += e[j];
            }
            float inv = 1.f / sum;
#pragma unroll
            for (int j = 0; j < NM + 1; j++) sm->Sc[i][h][j] = e[j] * inv;
        }
        __syncthreads();

        // --- O = A @ V  (writes swizzled Os) ------------------------------------
#pragma unroll
        for (int rep = 0; rep < 8; rep++) {
            int idx = rep * SCAN_THREADS + tid;
            int i = idx >> 9, c = idx & (DD - 1), h = c >> 6;
            float o = 0.f;
#pragma unroll
            for (int j = 0; j < NM + 1; j++)
                o = fmaf(sm->Sc[i][h][j], sm->Vs[j][c], o);
            Osf[swf(idx)] = o;
        }
        __syncthreads();

        // --- out-projection tile + residual (f32x2, swizzled Os reads) ----------
        {
            unsigned long long acc[NM];
#pragma unroll
            for (int i = 0; i < NM; i++) acc[i] = 0ull;
#pragma unroll 4
            for (int kk = 0; kk < 16; kk++) {
                ulonglong2 wo = Wp[(48 + kk) * 4096 + wbase];
                const int c0 = (ks * 16 + kk) ^ ks;
#pragma unroll
                for (int i = 0; i < NM; i++) {
                    ulonglong2 x = *(const ulonglong2*)(Os4 + i * 128 + c0);
                    fma2(acc[i], x.x, wo.x);
                    fma2(acc[i], x.y, wo.y);
                }
            }
#pragma unroll
            for (int i = 0; i < NM; i++) {
                float2 f = u2f2(acc[i]);
                float a = f.x + f.y;
                a += __shfl_xor_sync(0xffffffffu, a, 1);
                a += __shfl_xor_sync(0xffffffffu, a, 2);
                a += __shfl_xor_sync(0xffffffffu, a, 4);
                if (ks == 0) {
                    float r = Xsf[swf(i * DD + col)] + a + bo_r;
                    sm->resid[i][colLocal] = r;
                    g_resid[b][i][col] = r;
                }
            }
        }
        __syncthreads();

        // --- LN partial stats over this CTA's 64 columns -------------------------
        {
            int i = tid >> 6, c = tid & 63;
            float v = sm->resid[i][c];
            float s1 = v, s2 = v * v;
#pragma unroll
            for (int off = 16; off; off >>= 1) {
                s1 += __shfl_xor_sync(0xffffffffu, s1, off);
                s2 += __shfl_xor_sync(0xffffffffu, s2, off);
            }
            if ((tid & 31) == 0) {
                int half = (tid >> 5) & 1;
                sm->wpart[i][half][0] = s1;
                sm->wpart[i][half][1] = s2;
            }
        }
        __syncthreads();
        if (tid < NM) {
            g_part[b][rank][tid][0] = sm->wpart[tid][0][0] + sm->wpart[tid][1][0];
            g_part[b][rank][tid][1] = sm->wpart[tid][0][1] + sm->wpart[tid][1][1];
        }
        cluster_sync_all();   // #2: resid + partial stats visible

        // --- LN finalize (redundantly per CTA), rebuild full swizzled Xs ----------
        if (tid < NM) {
            float S = 0.f, SS = 0.f;
#pragma unroll
            for (int r2 = 0; r2 < CSIZE; r2++) {
                S  += g_part[b][r2][tid][0];
                SS += g_part[b][r2][tid][1];
            }
            float mu = S * (1.f / 512.f);
            float var = SS * (1.f / 512.f) - mu * mu;
            sm->muinv[tid][0] = mu;
            sm->muinv[tid][1] = rsqrtf(var + 1e-5f);
        }
        __syncthreads();
        {
            const float4* rsrc = (const float4*)&g_resid[b][0][0];
            float4* xd = (float4*)sm->Xs;
            {
                int v = tid;
                int i = v >> 7;
                float mu = sm->muinv[i][0], inv = sm->muinv[i][1];
                float4 r = rsrc[v];
                float4 y;
                y.x = (r.x - mu) * inv * lng0.x + lnb0.x;
                y.y = (r.y - mu) * inv * lng0.y + lnb0.y;
                y.z = (r.z - mu) * inv * lng0.z + lnb0.z;
                y.w = (r.w - mu) * inv * lng0.w + lnb0.w;
                xd[sw16(v)] = y;
            }
            {
                int v = tid + 512;
                int i = v >> 7;
                float mu = sm->muinv[i][0], inv = sm->muinv[i][1];
                float4 r = rsrc[v];
                float4 y;
                y.x = (r.x - mu) * inv * lng1.x + lnb1.x;
                y.y = (r.y - mu) * inv * lng1.y + lnb1.y;
                y.z = (r.z - mu) * inv * lng1.z + lnb1.z;
                y.w = (r.w - mu) * inv * lng1.w + lnb1.w;
                xd[sw16(v)] = y;
            }
        }
        __syncthreads();

        // --- summary (own 64 columns) ---------------------------------------------
        if (tid < 64) {
            int c = rank * 64 + tid;
            float s = 0.f;
#pragma unroll
            for (int i = 0; i < NM; i++) s += Xsf[swf(i * DD + c)];
            g_MS[b * TT + t][c] = s * 0.125f;
        }
        __syncthreads();
    }
}

// ---------------------------------------------------------------------------
// Launch
// ---------------------------------------------------------------------------
extern "C" void kernel_launch(void* const* d_in, const int* in_sizes, int n_in,
                              void* d_out, int out_size) {
    const int*   ids        = (const int*)d_in[0];
    const float* embedding  = (const float*)d_in[1];
    const float* mem_init   = (const float*)d_in[2];
    const float* in_proj_w  = (const float*)d_in[3];
    const float* in_proj_b  = (const float*)d_in[4];
    const float* out_proj_w = (const float*)d_in[5];
    const float* out_proj_b = (const float*)d_in[6];
    const float* ln_g       = (const float*)d_in[7];
    const float* ln_b       = (const float*)d_in[8];
    const float* proj_w     = (const float*)d_in[9];
    const float* proj_b     = (const float*)d_in[10];
    float* out = (float*)d_out;

    void *pKVy = nullptr, *pMS = nullptr;
    cudaGetSymbolAddress(&pKVy, g_KVy);
    cudaGetSymbolAddress(&pMS, g_MS);

    cudaFuncSetAttribute(scan_kernel,
                         cudaFuncAttributeMaxDynamicSharedMemorySize,
                         (int)sizeof(SmemScan));

    // 1) repack weights for coalesced per-step loads
    repack_kernel<<<4096, 256>>>(in_proj_w, out_proj_w);

    // 2) precompute K,V projections of all tokens (gather GEMM)
    {
        dim3 grid((2 * DD) / 128, (NB * TT) / 128);
        gemm_nt<true, false><<<grid, 256>>>(
            nullptr, ids, embedding,
            in_proj_w + (size_t)DD * DD, in_proj_b + DD,
            (float*)pKVy, NB * TT, 2 * DD);
    }

    // 3) sequential scan: 16 clusters (one per batch) x 8 CTAs
    scan_kernel<<<dim3(CSIZE, NB), SCAN_THREADS, sizeof(SmemScan)>>>(
        mem_init, in_proj_b, out_proj_b, ln_g, ln_b);

    // 4) final projection: relu(MS @ proj_w^T + proj_b)
    {
        dim3 grid(OUTF / 128, (NB * TT) / 128);
        gemm_nt<false, true><<<grid, 256>>>(
            (const float*)pMS, nullptr, nullptr,
            proj_w, proj_b, out, NB * TT, OUTF);
    }
}

// round 9
// speedup vs baseline: 8.0091x; 1.2029x over previous
#include <cuda_runtime.h>
#include <math.h>

// Problem dims
#define NB   16
#define TT   512
#define DD   512
#define NM   8
#define NH   8
#define DHD  64
#define OUTF 2048
#define CSIZE 8
#define SCAN_THREADS 512

// ---------------------------------------------------------------------------
// Scratch (static __device__ — no allocations allowed)
// ---------------------------------------------------------------------------
__device__ __align__(16) float g_Wpack[4 * 16 * 512 * 8 * 4]; // [pp][kk][col][ks][4]
__device__ __align__(16) float g_O[NB][NM][DD];               // attention out exchange
__device__ __align__(16) float g_resid[NB][NM][DD];           // residual (pre-LN)
__device__ float g_part[NB][CSIZE][NM][2];                    // LN partial (sum, sumsq)
__device__ __align__(16) float g_KVy[NB * TT][2 * DD];        // precomputed K,V of y_t
__device__ __align__(16) float g_MS[NB * TT][DD];             // summaries

// ---------------------------------------------------------------------------
// f32x2 packed helpers
// ---------------------------------------------------------------------------
__device__ __forceinline__ void fma2(unsigned long long& d,
                                     unsigned long long a, unsigned long long b) {
    asm("fma.rn.f32x2 %0, %1, %2, %0;" : "+l"(d) : "l"(a), "l"(b));
}
__device__ __forceinline__ float2 u2f2(unsigned long long v) {
    float2 f; asm("mov.b64 {%0,%1}, %2;" : "=f"(f.x), "=f"(f.y) : "l"(v)); return f;
}

// 16B-chunk swizzle (conflict-free ks-strided reads)
__device__ __forceinline__ int sw16(int v) { return v ^ ((v >> 4) & 7); }
__device__ __forceinline__ int swf(int f) {
    int c = f >> 2;
    return (c ^ ((c >> 4) & 7)) * 4 + (f & 3);
}

// ---------------------------------------------------------------------------
// Weight repack: g_Wpack[(((pp*16+kk)*512+col)*8+ks)*4+e] = W[col][ks*64+kk*4+e]
// ---------------------------------------------------------------------------
__global__ void repack_kernel(const float* __restrict__ Wqkv,
                              const float* __restrict__ Wo) {
    int idx = blockIdx.x * 256 + threadIdx.x;   // 0 .. 2^20-1
    int e   = idx & 3;
    int ks  = (idx >> 2) & 7;
    int col = (idx >> 5) & 511;
    int kk  = (idx >> 14) & 15;
    int pp  = idx >> 18;
    int k   = ks * 64 + kk * 4 + e;
    float v = (pp < 3) ? Wqkv[((size_t)(pp * 512 + col)) * 512 + k]
                       : Wo[(size_t)col * 512 + k];
    g_Wpack[idx] = v;
}

__global__ void dummy_kernel() {}

// ---------------------------------------------------------------------------
// Generic GEMM-NT: C = act(bias + A @ W^T), K=512
// ---------------------------------------------------------------------------
template <bool GATHER, bool RELU>
__global__ __launch_bounds__(256) void gemm_nt(
    const float* __restrict__ A, const int* __restrict__ ids,
    const float* __restrict__ emb,
    const float* __restrict__ W, const float* __restrict__ bias,
    float* __restrict__ C, int M, int N)
{
    __shared__ float As[16][132];
    __shared__ float Bs[16][132];

    const int tid = threadIdx.x;
    const int ty = tid >> 4;
    const int tx = tid & 15;
    const int m0 = blockIdx.y * 128;
    const int n0 = blockIdx.x * 128;

    float acc[8][8];
#pragma unroll
    for (int i = 0; i < 8; i++)
#pragma unroll
        for (int j = 0; j < 8; j++) acc[i][j] = 0.f;

    for (int kt = 0; kt < 512; kt += 16) {
#pragma unroll
        for (int s = 0; s < 2; s++) {
            int slot = tid + s * 256;
            int r = slot >> 2;
            int q = (slot & 3) * 4;
            float4 v, w;
            if (GATHER) {
                int id = ids[m0 + r];
                if (id != 0)
                    v = *(const float4*)(emb + (size_t)id * 512 + kt + q);
                else
                    v = make_float4(0.f, 0.f, 0.f, 0.f);
            } else {
                v = *(const float4*)(A + (size_t)(m0 + r) * 512 + kt + q);
            }
            w = *(const float4*)(W + (size_t)(n0 + r) * 512 + kt + q);
            As[q + 0][r] = v.x; As[q + 1][r] = v.y;
            As[q + 2][r] = v.z; As[q + 3][r] = v.w;
            Bs[q + 0][r] = w.x; Bs[q + 1][r] = w.y;
            Bs[q + 2][r] = w.z; Bs[q + 3][r] = w.w;
        }
        __syncthreads();
#pragma unroll
        for (int kk = 0; kk < 16; kk++) {
            const float4 a0 = *(const float4*)&As[kk][ty * 8];
            const float4 a1 = *(const float4*)&As[kk][ty * 8 + 4];
            const float4 b0 = *(const float4*)&Bs[kk][tx * 8];
            const float4 b1 = *(const float4*)&Bs[kk][tx * 8 + 4];
            float ar[8] = {a0.x, a0.y, a0.z, a0.w, a1.x, a1.y, a1.z, a1.w};
            float br[8] = {b0.x, b0.y, b0.z, b0.w, b1.x, b1.y, b1.z, b1.w};
#pragma unroll
            for (int i = 0; i < 8; i++)
#pragma unroll
                for (int j = 0; j < 8; j++)
                    acc[i][j] = fmaf(ar[i], br[j], acc[i][j]);
        }
        __syncthreads();
    }

#pragma unroll
    for (int i = 0; i < 8; i++) {
        int m = m0 + ty * 8 + i;
#pragma unroll
        for (int j = 0; j < 8; j++) {
            int n = n0 + tx * 8 + j;
            float v = acc[i][j] + bias[n];
            if (RELU) v = fmaxf(v, 0.f);
            C[(size_t)m * N + n] = v;
        }
    }
}

// ---------------------------------------------------------------------------
// Scan kernel: one cluster of 8 CTAs per batch, 512 threads per CTA.
// CTA `rank` owns columns [64r, 64r+64) == head r. Attention is fully local.
// Only O (attention output) and resid/stats are exchanged cluster-wide.
// ---------------------------------------------------------------------------
struct SmemScan {
    float Xs[NM][DD];            // normalized state (SWIZZLED)
    float Os[NM][DD];            // full attention output (SWIZZLED)
    float Qs[NM][68];            // own head's q (pad 68 -> conflict-free rows)
    float Ks2[NM + 1][68];       // own head's k (+ y row)
    float Vs2[NM + 1][68];       // own head's v (+ y row)
    float Sc[NM][12];            // scores / attn weights for own head
    float resid[NM][64];
    float wpart[NM][2][2];
    float muinv[NM][2];
};

__global__ __launch_bounds__(SCAN_THREADS, 1) __cluster_dims__(CSIZE, 1, 1)
void scan_kernel(const float* __restrict__ mem_init,
                 const float* __restrict__ bqkv,
                 const float* __restrict__ bo,
                 const float* __restrict__ lng, const float* __restrict__ lnb)
{
    __shared__ SmemScan sm_s;
    SmemScan* sm = &sm_s;

    const int tid = threadIdx.x;
    const int rank = blockIdx.x;          // 0..7 == cluster cta rank == head
    const int b = blockIdx.y;             // batch
    const int colLocal = tid >> 3;        // 0..63
    const int col = rank * 64 + colLocal; // global output column
    const int ks = tid & 7;               // k-split lane
    const ulonglong2* Wp = (const ulonglong2*)g_Wpack;
    const int wbase = col * 8 + ks;

    const float4* Xs4 = (const float4*)sm->Xs;
    const float4* Os4 = (const float4*)sm->Os;
    float* Xsf = (float*)sm->Xs;

    // Hoisted per-thread constants
    const float bq_r = bqkv[col];
    const float bk_r = bqkv[DD + col];
    const float bv_r = bqkv[2 * DD + col];
    const float bo_r = bo[col];
    const float4 lng0 = ((const float4*)lng)[tid & 127];
    const float4 lnb0 = ((const float4*)lnb)[tid & 127];
    const float4 lng1 = ((const float4*)lng)[(tid + 512) & 127];
    const float4 lnb1 = ((const float4*)lnb)[(tid + 512) & 127];

    // Init Xs = mem_init (M0 broadcast), swizzled
    {
        const float4* src = (const float4*)mem_init;
        float4* xd = (float4*)sm->Xs;
        xd[sw16(tid)] = src[tid];
        xd[sw16(tid + 512)] = src[tid + 512];
    }
    __syncthreads();

    for (int t = 0; t < TT; t++) {
        // --- prefetch y_t's k,v head-slice into row 8 ---------------------------
        if (tid < 32) {
            const float4* kvy = (const float4*)&g_KVy[b * TT + t][0];
            int q = tid & 15;
            if (tid < 16) {
                float4 v = kvy[rank * 16 + q];
                *(float4*)&sm->Ks2[NM][q * 4] = v;
            } else {
                float4 v = kvy[128 + rank * 16 + q];
                *(float4*)&sm->Vs2[NM][q * 4] = v;
            }
        }

        // --- phase 1: fused Q/K/V projections for own 64 cols (f32x2) -----------
        {
            unsigned long long acc[3][NM];
#pragma unroll
            for (int p = 0; p < 3; p++)
#pragma unroll
                for (int i = 0; i < NM; i++) acc[p][i] = 0ull;

#pragma unroll 4
            for (int kk = 0; kk < 16; kk++) {
                ulonglong2 wq = Wp[(kk)*4096 + wbase];
                ulonglong2 wk = Wp[(16 + kk) * 4096 + wbase];
                ulonglong2 wv = Wp[(32 + kk) * 4096 + wbase];
                const int c0 = (ks * 16 + kk) ^ ks;   // swizzled chunk
#pragma unroll
                for (int i = 0; i < NM; i++) {
                    ulonglong2 x = *(const ulonglong2*)(Xs4 + i * 128 + c0);
                    fma2(acc[0][i], x.x, wq.x); fma2(acc[0][i], x.y, wq.y);
                    fma2(acc[1][i], x.x, wk.x); fma2(acc[1][i], x.y, wk.y);
                    fma2(acc[2][i], x.x, wv.x); fma2(acc[2][i], x.y, wv.y);
                }
            }
#pragma unroll
            for (int p = 0; p < 3; p++) {
                float bias = (p == 0) ? bq_r : (p == 1) ? bk_r : bv_r;
#pragma unroll
                for (int i = 0; i < NM; i++) {
                    float2 f = u2f2(acc[p][i]);
                    float a = f.x + f.y;
                    a += __shfl_xor_sync(0xffffffffu, a, 1);
                    a += __shfl_xor_sync(0xffffffffu, a, 2);
                    a += __shfl_xor_sync(0xffffffffu, a, 4);
                    if (ks == 0) {
                        float r = a + bias;
                        if (p == 0)      sm->Qs[i][colLocal]  = r;
                        else if (p == 1) sm->Ks2[i][colLocal] = r;
                        else             sm->Vs2[i][colLocal] = r;
                    }
                }
            }
        }
        __syncthreads();

        // --- scores for own head: s[i][j] = q_i . k_j / 8 (72 dots of len 64) ----
        if (tid < NM * (NM + 1)) {
            int i = tid / (NM + 1);
            int j = tid - i * (NM + 1);
            const float* q = sm->Qs[i];
            const float* kr = sm->Ks2[j];
            float s = 0.f;
#pragma unroll
            for (int d = 0; d < DHD; d += 4) {
                float4 a = *(const float4*)(q + d);
                float4 c = *(const float4*)(kr + d);
                s = fmaf(a.x, c.x, fmaf(a.y, c.y,
                     fmaf(a.z, c.z, fmaf(a.w, c.w, s))));
            }
            sm->Sc[i][j] = s * 0.125f;
        }
        __syncthreads();

        // --- softmax over 9 entries (8 threads) ----------------------------------
        if (tid < NM) {
            float mx = -1e30f;
#pragma unroll
            for (int j = 0; j < NM + 1; j++) mx = fmaxf(mx, sm->Sc[tid][j]);
            float e[NM + 1];
            float sum = 0.f;
#pragma unroll
            for (int j = 0; j < NM + 1; j++) {
                e[j] = expf(sm->Sc[tid][j] - mx);
                sum += e[j];
            }
            float inv = 1.f / sum;
#pragma unroll
            for (int j = 0; j < NM + 1; j++) sm->Sc[tid][j] = e[j] * inv;
        }
        __syncthreads();

        // --- O slice = A @ V (own head), write to exchange buffer ----------------
        {
            int i = tid >> 6, c = tid & 63;
            float o = 0.f;
#pragma unroll
            for (int j = 0; j < NM + 1; j++)
                o = fmaf(sm->Sc[i][j], sm->Vs2[j][c], o);
            g_O[b][i][rank * 64 + c] = o;
        }

        // --- cluster barrier #1 (O exchange); prefetch out-proj weights ----------
        ulonglong2 wo[16];
        asm volatile("barrier.cluster.arrive.aligned;" ::: "memory");
#pragma unroll
        for (int kk = 0; kk < 16; kk++)
            wo[kk] = Wp[(48 + kk) * 4096 + wbase];
        asm volatile("barrier.cluster.wait.aligned;" ::: "memory");

        // --- load full O into swizzled smem --------------------------------------
        {
            const float4* osrc = (const float4*)&g_O[b][0][0];
            float4* od = (float4*)sm->Os;
            od[sw16(tid)] = osrc[tid];
            od[sw16(tid + 512)] = osrc[tid + 512];
        }
        __syncthreads();

        // --- out-projection tile + residual (weights from regs) ------------------
        {
            unsigned long long acc[NM];
#pragma unroll
            for (int i = 0; i < NM; i++) acc[i] = 0ull;
#pragma unroll 4
            for (int kk = 0; kk < 16; kk++) {
                const int c0 = (ks * 16 + kk) ^ ks;
#pragma unroll
                for (int i = 0; i < NM; i++) {
                    ulonglong2 x = *(const ulonglong2*)(Os4 + i * 128 + c0);
                    fma2(acc[i], x.x, wo[kk].x);
                    fma2(acc[i], x.y, wo[kk].y);
                }
            }
#pragma unroll
            for (int i = 0; i < NM; i++) {
                float2 f = u2f2(acc[i]);
                float a = f.x + f.y;
                a += __shfl_xor_sync(0xffffffffu, a, 1);
                a += __shfl_xor_sync(0xffffffffu, a, 2);
                a += __shfl_xor_sync(0xffffffffu, a, 4);
                if (ks == 0) {
                    float r = Xsf[swf(i * DD + col)] + a + bo_r;
                    sm->resid[i][colLocal] = r;
                    g_resid[b][i][col] = r;
                }
            }
        }
        __syncthreads();

        // --- LN partial stats over own 64 columns --------------------------------
        {
            int i = tid >> 6, c = tid & 63;
            float v = sm->resid[i][c];
            float s1 = v, s2 = v * v;
#pragma unroll
            for (int off = 16; off; off >>= 1) {
                s1 += __shfl_xor_sync(0xffffffffu, s1, off);
                s2 += __shfl_xor_sync(0xffffffffu, s2, off);
            }
            if ((tid & 31) == 0) {
                int half = (tid >> 5) & 1;
                sm->wpart[i][half][0] = s1;
                sm->wpart[i][half][1] = s2;
            }
        }
        __syncthreads();
        if (tid < NM) {
            g_part[b][rank][tid][0] = sm->wpart[tid][0][0] + sm->wpart[tid][1][0];
            g_part[b][rank][tid][1] = sm->wpart[tid][0][1] + sm->wpart[tid][1][1];
        }
        asm volatile("barrier.cluster.arrive.aligned;" ::: "memory");
        asm volatile("barrier.cluster.wait.aligned;" ::: "memory");   // #2

        // --- LN finalize (redundant per CTA), rebuild full swizzled Xs ------------
        if (tid < NM) {
            float S = 0.f, SS = 0.f;
#pragma unroll
            for (int r2 = 0; r2 < CSIZE; r2++) {
                S  += g_part[b][r2][tid][0];
                SS += g_part[b][r2][tid][1];
            }
            float mu = S * (1.f / 512.f);
            float var = SS * (1.f / 512.f) - mu * mu;
            sm->muinv[tid][0] = mu;
            sm->muinv[tid][1] = rsqrtf(var + 1e-5f);
        }
        __syncthreads();
        {
            const float4* rsrc = (const float4*)&g_resid[b][0][0];
            float4* xd = (float4*)sm->Xs;
            {
                int v = tid;
                int i = v >> 7;
                float mu = sm->muinv[i][0], inv = sm->muinv[i][1];
                float4 r = rsrc[v];
                float4 y;
                y.x = (r.x - mu) * inv * lng0.x + lnb0.x;
                y.y = (r.y - mu) * inv * lng0.y + lnb0.y;
                y.z = (r.z - mu) * inv * lng0.z + lnb0.z;
                y.w = (r.w - mu) * inv * lng0.w + lnb0.w;
                xd[sw16(v)] = y;
            }
            {
                int v = tid + 512;
                int i = v >> 7;
                float mu = sm->muinv[i][0], inv = sm->muinv[i][1];
                float4 r = rsrc[v];
                float4 y;
                y.x = (r.x - mu) * inv * lng1.x + lnb1.x;
                y.y = (r.y - mu) * inv * lng1.y + lnb1.y;
                y.z = (r.z - mu) * inv * lng1.z + lnb1.z;
                y.w = (r.w - mu) * inv * lng1.w + lnb1.w;
                xd[sw16(v)] = y;
            }
        }
        __syncthreads();

        // --- summary (own 64 columns) ---------------------------------------------
        if (tid < 64) {
            int c = rank * 64 + tid;
            float s = 0.f;
#pragma unroll
            for (int i = 0; i < NM; i++) s += Xsf[swf(i * DD + c)];
            g_MS[b * TT + t][c] = s * 0.125f;
        }
        __syncthreads();
    }
}

// ---------------------------------------------------------------------------
// Launch
// ---------------------------------------------------------------------------
extern "C" void kernel_launch(void* const* d_in, const int* in_sizes, int n_in,
                              void* d_out, int out_size) {
    const int*   ids        = (const int*)d_in[0];
    const float* embedding  = (const float*)d_in[1];
    const float* mem_init   = (const float*)d_in[2];
    const float* in_proj_w  = (const float*)d_in[3];
    const float* in_proj_b  = (const float*)d_in[4];
    const float* out_proj_w = (const float*)d_in[5];
    const float* out_proj_b = (const float*)d_in[6];
    const float* ln_g       = (const float*)d_in[7];
    const float* ln_b       = (const float*)d_in[8];
    const float* proj_w     = (const float*)d_in[9];
    const float* proj_b     = (const float*)d_in[10];
    float* out = (float*)d_out;

    void *pKVy = nullptr, *pMS = nullptr;
    cudaGetSymbolAddress(&pKVy, g_KVy);
    cudaGetSymbolAddress(&pMS, g_MS);

    // 1) repack weights for coalesced per-step loads          (launch 0)
    repack_kernel<<<4096, 256>>>(in_proj_w, out_proj_w);

    // 2) precompute K,V projections of all tokens (gather GEMM)  (launch 1)
    {
        dim3 grid((2 * DD) / 128, (NB * TT) / 128);
        gemm_nt<true, false><<<grid, 256>>>(
            nullptr, ids, embedding,
            in_proj_w + (size_t)DD * DD, in_proj_b + DD,
            (float*)pKVy, NB * TT, 2 * DD);
    }

    // padding launches so ncu (-s 5 -c 1) profiles the scan    (launches 2,3,4)
    dummy_kernel<<<1, 32>>>();
    dummy_kernel<<<1, 32>>>();
    dummy_kernel<<<1, 32>>>();

    // 3) sequential scan: 16 clusters (one per batch) x 8 CTAs  (launch 5)
    scan_kernel<<<dim3(CSIZE, NB), SCAN_THREADS>>>(
        mem_init, in_proj_b, out_proj_b, ln_g, ln_b);

    // 4) final projection: relu(MS @ proj_w^T + proj_b)         (launch 6)
    {
        dim3 grid(OUTF / 128, (NB * TT) / 128);
        gemm_nt<false, true><<<grid, 256>>>(
            (const float*)pMS, nullptr, nullptr,
            proj_w, proj_b, out, NB * TT, OUTF);
    }
}

// round 10
// speedup vs baseline: 9.7701x; 1.2199x over previous
#include <cuda_runtime.h>
#include <math.h>

// Problem dims
#define NB   16
#define TT   512
#define DD   512
#define NM   8
#define NH   8
#define DHD  64
#define OUTF 2048
#define CSIZE 8
#define SCAN_THREADS 512

// ---------------------------------------------------------------------------
// Scratch (static __device__ — no allocations allowed)
// ---------------------------------------------------------------------------
__device__ __align__(16) float g_Wpack[4 * 16 * 8 * 512 * 4]; // [pp][kk][ks][col][4]
__device__ __align__(16) float g_O[NB][NM][DD];               // attention out exchange
__device__ __align__(16) float g_resid[NB][NM][DD];           // residual (pre-LN)
__device__ float g_part[NB][CSIZE][NM][2];                    // LN partial (sum, sumsq)
__device__ __align__(16) float g_KVy[NB * TT][2 * DD];        // precomputed K,V of y_t
__device__ __align__(16) float g_MS[NB * TT][DD];             // summaries

// ---------------------------------------------------------------------------
// f32x2 packed helpers
// ---------------------------------------------------------------------------
__device__ __forceinline__ void fma2(unsigned long long& d,
                                     unsigned long long a, unsigned long long b) {
    asm("fma.rn.f32x2 %0, %1, %2, %0;" : "+l"(d) : "l"(a), "l"(b));
}
__device__ __forceinline__ float2 u2f2(unsigned long long v) {
    float2 f; asm("mov.b64 {%0,%1}, %2;" : "=f"(f.x), "=f"(f.y) : "l"(v)); return f;
}

// ---------------------------------------------------------------------------
// Weight repack: g_Wpack[(((pp*16+kk)*8+ks)*512+col)*4+e] = W[col][ks*64+kk*4+e]
// Warp = 32 consecutive cols, same ks -> 512B contiguous LDG per warp.
// ---------------------------------------------------------------------------
__global__ void repack_kernel(const float* __restrict__ Wqkv,
                              const float* __restrict__ Wo) {
    int idx = blockIdx.x * 256 + threadIdx.x;   // 0 .. 2^20-1
    int e   = idx & 3;
    int col = (idx >> 2) & 511;
    int ks  = (idx >> 11) & 7;
    int kk  = (idx >> 14) & 15;
    int pp  = idx >> 18;
    int k   = ks * 64 + kk * 4 + e;
    float v = (pp < 3) ? Wqkv[((size_t)(pp * 512 + col)) * 512 + k]
                       : Wo[(size_t)col * 512 + k];
    g_Wpack[idx] = v;
}

__global__ void dummy_kernel() {}

// ---------------------------------------------------------------------------
// Generic GEMM-NT: C = act(bias + A @ W^T), K=512
// ---------------------------------------------------------------------------
template <bool GATHER, bool RELU>
__global__ __launch_bounds__(256) void gemm_nt(
    const float* __restrict__ A, const int* __restrict__ ids,
    const float* __restrict__ emb,
    const float* __restrict__ W, const float* __restrict__ bias,
    float* __restrict__ C, int M, int N)
{
    __shared__ float As[16][132];
    __shared__ float Bs[16][132];

    const int tid = threadIdx.x;
    const int ty = tid >> 4;
    const int tx = tid & 15;
    const int m0 = blockIdx.y * 128;
    const int n0 = blockIdx.x * 128;

    float acc[8][8];
#pragma unroll
    for (int i = 0; i < 8; i++)
#pragma unroll
        for (int j = 0; j < 8; j++) acc[i][j] = 0.f;

    for (int kt = 0; kt < 512; kt += 16) {
#pragma unroll
        for (int s = 0; s < 2; s++) {
            int slot = tid + s * 256;
            int r = slot >> 2;
            int q = (slot & 3) * 4;
            float4 v, w;
            if (GATHER) {
                int id = ids[m0 + r];
                if (id != 0)
                    v = *(const float4*)(emb + (size_t)id * 512 + kt + q);
                else
                    v = make_float4(0.f, 0.f, 0.f, 0.f);
            } else {
                v = *(const float4*)(A + (size_t)(m0 + r) * 512 + kt + q);
            }
            w = *(const float4*)(W + (size_t)(n0 + r) * 512 + kt + q);
            As[q + 0][r] = v.x; As[q + 1][r] = v.y;
            As[q + 2][r] = v.z; As[q + 3][r] = v.w;
            Bs[q + 0][r] = w.x; Bs[q + 1][r] = w.y;
            Bs[q + 2][r] = w.z; Bs[q + 3][r] = w.w;
        }
        __syncthreads();
#pragma unroll
        for (int kk = 0; kk < 16; kk++) {
            const float4 a0 = *(const float4*)&As[kk][ty * 8];
            const float4 a1 = *(const float4*)&As[kk][ty * 8 + 4];
            const float4 b0 = *(const float4*)&Bs[kk][tx * 8];
            const float4 b1 = *(const float4*)&Bs[kk][tx * 8 + 4];
            float ar[8] = {a0.x, a0.y, a0.z, a0.w, a1.x, a1.y, a1.z, a1.w};
            float br[8] = {b0.x, b0.y, b0.z, b0.w, b1.x, b1.y, b1.z, b1.w};
#pragma unroll
            for (int i = 0; i < 8; i++)
#pragma unroll
                for (int j = 0; j < 8; j++)
                    acc[i][j] = fmaf(ar[i], br[j], acc[i][j]);
        }
        __syncthreads();
    }

#pragma unroll
    for (int i = 0; i < 8; i++) {
        int m = m0 + ty * 8 + i;
#pragma unroll
        for (int j = 0; j < 8; j++) {
            int n = n0 + tx * 8 + j;
            float v = acc[i][j] + bias[n];
            if (RELU) v = fmaxf(v, 0.f);
            C[(size_t)m * N + n] = v;
        }
    }
}

// ---------------------------------------------------------------------------
// Scan kernel: one cluster of 8 CTAs per batch, 512 threads per CTA.
// CTA `rank` owns columns [64r, 64r+64) == head r. Attention is fully local.
// Thread layout: ks = tid>>6 (k-slice), col = tid&63 -> X/O reads are warp
// broadcasts; k-reduction via conflict-free smem partials (no shuffles).
// ---------------------------------------------------------------------------
struct SmemScan {
    float Xs[NM][DD];            // normalized state (plain layout)
    float Os[NM][DD];            // full attention output (plain layout)
    float part[3 * NM * 8 * 64]; // k-split partials [p][i][ks][col]
    float Qs[NM][68];
    float Ks2[NM + 1][68];
    float Vs2[NM + 1][68];
    float Sc[NM][12];
    float wpart[NM][2][2];
    float muinv[NM][2];
};

__global__ __launch_bounds__(SCAN_THREADS, 1) __cluster_dims__(CSIZE, 1, 1)
void scan_kernel(const float* __restrict__ mem_init,
                 const float* __restrict__ bqkv,
                 const float* __restrict__ bo,
                 const float* __restrict__ lng, const float* __restrict__ lnb)
{
    extern __shared__ char smem_raw[];
    SmemScan* sm = (SmemScan*)smem_raw;

    const int tid = threadIdx.x;
    const int rank = blockIdx.x;          // 0..7 == cluster cta rank == head
    const int b = blockIdx.y;             // batch
    const int ks = tid >> 6;              // k-slice (constant per warp-pair)
    const int cl = tid & 63;              // column within head
    const int col = rank * 64 + cl;       // global column
    const ulonglong2* Wp = (const ulonglong2*)g_Wpack;

    const float4* Xs4 = (const float4*)sm->Xs;
    const float4* Os4 = (const float4*)sm->Os;
    float* Xsf = (float*)sm->Xs;

    // Hoisted per-thread constants (consumer mapping: i = tid>>6, c = tid&63)
    const float bq2 = bqkv[col];
    const float bk2 = bqkv[DD + col];
    const float bv2 = bqkv[2 * DD + col];
    const float bo2 = bo[col];
    const float4 lng0 = ((const float4*)lng)[tid & 127];
    const float4 lnb0 = ((const float4*)lnb)[tid & 127];
    const float4 lng1 = ((const float4*)lng)[(tid + 512) & 127];
    const float4 lnb1 = ((const float4*)lnb)[(tid + 512) & 127];

    // Init Xs = mem_init (M0 broadcast)
    {
        const float4* src = (const float4*)mem_init;
        float4* xd = (float4*)sm->Xs;
        xd[tid] = src[tid];
        xd[tid + 512] = src[tid + 512];
    }
    __syncthreads();

    for (int t = 0; t < TT; t++) {
        // --- prefetch y_t's k,v head-slice into row 8 ---------------------------
        if (tid < 32) {
            const float4* kvy = (const float4*)&g_KVy[b * TT + t][0];
            int q = tid & 15;
            if (tid < 16) {
                float4 v = kvy[rank * 16 + q];
                *(float4*)&sm->Ks2[NM][q * 4] = v;
            } else {
                float4 v = kvy[128 + rank * 16 + q];
                *(float4*)&sm->Vs2[NM][q * 4] = v;
            }
        }

        // --- phase 1: fused Q/K/V partial projections (broadcast X reads) -------
        {
            unsigned long long acc[3][NM];
#pragma unroll
            for (int p = 0; p < 3; p++)
#pragma unroll
                for (int i = 0; i < NM; i++) acc[p][i] = 0ull;

#pragma unroll 4
            for (int kk = 0; kk < 16; kk++) {
                const int wi = (kk * 8 + ks) * 512 + col;
                ulonglong2 wq = Wp[wi];
                ulonglong2 wk = Wp[wi + 65536];
                ulonglong2 wv = Wp[wi + 131072];
                const int xc = ks * 16 + kk;          // float4 chunk in row
#pragma unroll
                for (int i = 0; i < NM; i++) {
                    ulonglong2 x = *(const ulonglong2*)(Xs4 + i * 128 + xc);
                    fma2(acc[0][i], x.x, wq.x); fma2(acc[0][i], x.y, wq.y);
                    fma2(acc[1][i], x.x, wk.x); fma2(acc[1][i], x.y, wk.y);
                    fma2(acc[2][i], x.x, wv.x); fma2(acc[2][i], x.y, wv.y);
                }
            }
            // store partials [p][i][ks][col] (col-contiguous -> conflict-free)
#pragma unroll
            for (int p = 0; p < 3; p++)
#pragma unroll
                for (int i = 0; i < NM; i++) {
                    float2 f = u2f2(acc[p][i]);
                    sm->part[((p * NM + i) * 8 + ks) * 64 + cl] = f.x + f.y;
                }
        }
        __syncthreads();

        // --- k-reduction: 512 threads, (i = tid>>6, c = tid&63), 3 units each ----
        {
            int i = ks, c = cl;  // same decomposition
#pragma unroll
            for (int p = 0; p < 3; p++) {
                const float* pp = &sm->part[(p * NM + i) * 8 * 64 + c];
                float s = 0.f;
#pragma unroll
                for (int r2 = 0; r2 < 8; r2++) s += pp[r2 * 64];
                if (p == 0)      sm->Qs[i][c]  = s + bq2;
                else if (p == 1) sm->Ks2[i][c] = s + bk2;
                else             sm->Vs2[i][c] = s + bv2;
            }
        }
        __syncthreads();

        // --- scores for own head: s[i][j] = q_i . k_j / 8 ------------------------
        if (tid < NM * (NM + 1)) {
            int i = tid / (NM + 1);
            int j = tid - i * (NM + 1);
            const float* q = sm->Qs[i];
            const float* kr = sm->Ks2[j];
            float s = 0.f;
#pragma unroll
            for (int d = 0; d < DHD; d += 4) {
                float4 a = *(const float4*)(q + d);
                float4 c = *(const float4*)(kr + d);
                s = fmaf(a.x, c.x, fmaf(a.y, c.y,
                     fmaf(a.z, c.z, fmaf(a.w, c.w, s))));
            }
            sm->Sc[i][j] = s * 0.125f;
        }
        __syncthreads();

        // --- softmax over 9 entries (8 threads) ----------------------------------
        if (tid < NM) {
            float mx = -1e30f;
#pragma unroll
            for (int j = 0; j < NM + 1; j++) mx = fmaxf(mx, sm->Sc[tid][j]);
            float e[NM + 1];
            float sum = 0.f;
#pragma unroll
            for (int j = 0; j < NM + 1; j++) {
                e[j] = expf(sm->Sc[tid][j] - mx);
                sum += e[j];
            }
            float inv = 1.f / sum;
#pragma unroll
            for (int j = 0; j < NM + 1; j++) sm->Sc[tid][j] = e[j] * inv;
        }
        __syncthreads();

        // --- O slice = A @ V (own head), write to exchange buffer ----------------
        {
            int i = ks, c = cl;
            float o = 0.f;
#pragma unroll
            for (int j = 0; j < NM + 1; j++)
                o = fmaf(sm->Sc[i][j], sm->Vs2[j][c], o);
            g_O[b][i][rank * 64 + c] = o;
        }

        // --- cluster barrier #1 (O exchange); prefetch out-proj weights ----------
        ulonglong2 wo[16];
        asm volatile("barrier.cluster.arrive.aligned;" ::: "memory");
#pragma unroll
        for (int kk = 0; kk < 16; kk++)
            wo[kk] = Wp[196608 + (kk * 8 + ks) * 512 + col];
        asm volatile("barrier.cluster.wait.aligned;" ::: "memory");

        // --- load full O into smem ------------------------------------------------
        {
            const float4* osrc = (const float4*)&g_O[b][0][0];
            float4* od = (float4*)sm->Os;
            od[tid] = osrc[tid];
            od[tid + 512] = osrc[tid + 512];
        }
        __syncthreads();

        // --- out-projection partials (broadcast O reads, weights in regs) --------
        {
            unsigned long long acc[NM];
#pragma unroll
            for (int i = 0; i < NM; i++) acc[i] = 0ull;
#pragma unroll 4
            for (int kk = 0; kk < 16; kk++) {
                const int xc = ks * 16 + kk;
#pragma unroll
                for (int i = 0; i < NM; i++) {
                    ulonglong2 x = *(const ulonglong2*)(Os4 + i * 128 + xc);
                    fma2(acc[i], x.x, wo[kk].x);
                    fma2(acc[i], x.y, wo[kk].y);
                }
            }
#pragma unroll
            for (int i = 0; i < NM; i++) {
                float2 f = u2f2(acc[i]);
                sm->part[(i * 8 + ks) * 64 + cl] = f.x + f.y;
            }
        }
        __syncthreads();

        // --- reduce out-proj, residual, LN partial stats ---------------------------
        {
            int i = ks, c = cl;
            const float* pp = &sm->part[i * 8 * 64 + c];
            float s = 0.f;
#pragma unroll
            for (int r2 = 0; r2 < 8; r2++) s += pp[r2 * 64];
            float r = Xsf[i * DD + col] + s + bo2;
            g_resid[b][i][col] = r;

            float s1 = r, s2 = r * r;
#pragma unroll
            for (int off = 16; off; off >>= 1) {
                s1 += __shfl_xor_sync(0xffffffffu, s1, off);
                s2 += __shfl_xor_sync(0xffffffffu, s2, off);
            }
            if ((tid & 31) == 0) {
                int half = (tid >> 5) & 1;
                sm->wpart[i][half][0] = s1;
                sm->wpart[i][half][1] = s2;
            }
        }
        __syncthreads();
        if (tid < NM) {
            g_part[b][rank][tid][0] = sm->wpart[tid][0][0] + sm->wpart[tid][1][0];
            g_part[b][rank][tid][1] = sm->wpart[tid][0][1] + sm->wpart[tid][1][1];
        }
        asm volatile("barrier.cluster.arrive.aligned;" ::: "memory");
        asm volatile("barrier.cluster.wait.aligned;" ::: "memory");   // #2

        // --- LN finalize (redundant per CTA), rebuild full Xs ----------------------
        if (tid < NM) {
            float S = 0.f, SS = 0.f;
#pragma unroll
            for (int r2 = 0; r2 < CSIZE; r2++) {
                S  += g_part[b][r2][tid][0];
                SS += g_part[b][r2][tid][1];
            }
            float mu = S * (1.f / 512.f);
            float var = SS * (1.f / 512.f) - mu * mu;
            sm->muinv[tid][0] = mu;
            sm->muinv[tid][1] = rsqrtf(var + 1e-5f);
        }
        __syncthreads();
        {
            const float4* rsrc = (const float4*)&g_resid[b][0][0];
            float4* xd = (float4*)sm->Xs;
            {
                int v = tid;
                int i = v >> 7;
                float mu = sm->muinv[i][0], inv = sm->muinv[i][1];
                float4 r = rsrc[v];
                float4 y;
                y.x = (r.x - mu) * inv * lng0.x + lnb0.x;
                y.y = (r.y - mu) * inv * lng0.y + lnb0.y;
                y.z = (r.z - mu) * inv * lng0.z + lnb0.z;
                y.w = (r.w - mu) * inv * lng0.w + lnb0.w;
                xd[v] = y;
            }
            {
                int v = tid + 512;
                int i = v >> 7;
                float mu = sm->muinv[i][0], inv = sm->muinv[i][1];
                float4 r = rsrc[v];
                float4 y;
                y.x = (r.x - mu) * inv * lng1.x + lnb1.x;
                y.y = (r.y - mu) * inv * lng1.y + lnb1.y;
                y.z = (r.z - mu) * inv * lng1.z + lnb1.z;
                y.w = (r.w - mu) * inv * lng1.w + lnb1.w;
                xd[v] = y;
            }
        }
        __syncthreads();

        // --- summary (own 64 columns) ----------------------------------------------
        if (tid < 64) {
            int c = rank * 64 + tid;
            float s = 0.f;
#pragma unroll
            for (int i = 0; i < NM; i++) s += Xsf[i * DD + c];
            g_MS[b * TT + t][c] = s * 0.125f;
        }
        __syncthreads();
    }
}

// ---------------------------------------------------------------------------
// Launch
// ---------------------------------------------------------------------------
extern "C" void kernel_launch(void* const* d_in, const int* in_sizes, int n_in,
                              void* d_out, int out_size) {
    const int*   ids        = (const int*)d_in[0];
    const float* embedding  = (const float*)d_in[1];
    const float* mem_init   = (const float*)d_in[2];
    const float* in_proj_w  = (const float*)d_in[3];
    const float* in_proj_b  = (const float*)d_in[4];
    const float* out_proj_w = (const float*)d_in[5];
    const float* out_proj_b = (const float*)d_in[6];
    const float* ln_g       = (const float*)d_in[7];
    const float* ln_b       = (const float*)d_in[8];
    const float* proj_w     = (const float*)d_in[9];
    const float* proj_b     = (const float*)d_in[10];
    float* out = (float*)d_out;

    void *pKVy = nullptr, *pMS = nullptr;
    cudaGetSymbolAddress(&pKVy, g_KVy);
    cudaGetSymbolAddress(&pMS, g_MS);

    cudaFuncSetAttribute(scan_kernel,
                         cudaFuncAttributeMaxDynamicSharedMemorySize,
                         (int)sizeof(SmemScan));

    // 1) repack weights                                       (launch 0)
    repack_kernel<<<4096, 256>>>(in_proj_w, out_proj_w);

    // 2) precompute K,V projections of all tokens             (launch 1)
    {
        dim3 grid((2 * DD) / 128, (NB * TT) / 128);
        gemm_nt<true, false><<<grid, 256>>>(
            nullptr, ids, embedding,
            in_proj_w + (size_t)DD * DD, in_proj_b + DD,
            (float*)pKVy, NB * TT, 2 * DD);
    }

    // padding so ncu lands on the scan (profiled index = 3)   (launch 2)
    dummy_kernel<<<1, 32>>>();

    // 3) sequential scan: 16 clusters x 8 CTAs                (launch 3)
    scan_kernel<<<dim3(CSIZE, NB), SCAN_THREADS, sizeof(SmemScan)>>>(
        mem_init, in_proj_b, out_proj_b, ln_g, ln_b);

    // 4) final projection: relu(MS @ proj_w^T + proj_b)       (launch 4)
    {
        dim3 grid(OUTF / 128, (NB * TT) / 128);
        gemm_nt<false, true><<<grid, 256>>>(
            (const float*)pMS, nullptr, nullptr,
            proj_w, proj_b, out, NB * TT, OUTF);
    }
}